// round 13
// baseline (speedup 1.0000x reference)
#include <cuda_runtime.h>
#include <cuda_bf16.h>

// Fused Conv3d(8->8, k=3, same zero-pad) + sigmoid(gelu_tanh(relu(y))) + bias
// B=8, D=32, H=128, W=128. fp32, packed f32x2 FMAs.
//
// Round-13 (R10 base; R12's duplicated sS build regressed, reverted):
//  - 5 CTAs/SM: __launch_bounds__(128,5) (reg target ~100) + staging MLP
//    capped at 4 in-flight LDG.128 (frees ~16 regs vs full unroll).
//  - synchronous merged staging (all 3 depth slices per cin, one barrier
//    pair per cin); no cp.async (its smem cost would cap occupancy at 4).
//  - cooperative sS build (no duplicated rows -- R12 lesson).
// Thread: 2 output H rows x 4 W pixels x 8 couts (32 u64 accs). All f32x2
// operands are memory-aligned pairs. Weights in __constant__.

#define ROWP 132   // padded row stride in floats
#define SLROWS 10  // rows per staged slice
#define NROWS 30   // 3 slices

typedef unsigned long long u64;

__constant__ __align__(16) u64 cW[1728];     // splatted (w,w), [(ci*3+kd)*3+kh][kw*8+co]
__device__   __align__(16) u64 gW_buf[1728];

__device__ __forceinline__ void fma2(u64& d, u64 a, u64 b) {
    asm("fma.rn.f32x2 %0, %1, %2, %0;" : "+l"(d) : "l"(a), "l"(b));
}
__device__ __forceinline__ u64 pk2(float lo, float hi) {
    u64 r;
    asm("mov.b64 %0, {%1, %2};" : "=l"(r) : "f"(lo), "f"(hi));
    return r;
}
__device__ __forceinline__ float2 up2(u64 v) {
    float lo, hi;
    asm("mov.b64 {%0, %1}, %2;" : "=f"(lo), "=f"(hi) : "l"(v));
    return make_float2(lo, hi);
}
__device__ __forceinline__ float tanhapx(float x) {
    float r;
    asm("tanh.approx.f32 %0, %1;" : "=f"(r) : "f"(x));
    return r;
}

// sigmoid(gelu_tanh(relu(y))) via 2x tanh.approx
__device__ __forceinline__ float act_chain(float y) {
    float yr = fmaxf(y, 0.0f);
    float q  = fmaf(0.044715f * yr, yr, 1.0f);
    float t  = 0.7978845608028654f * yr * q;
    float hyr = 0.5f * yr;
    float g  = fmaf(hyr, tanhapx(t), hyr);
    return fmaf(0.5f, tanhapx(0.5f * g), 0.5f);
}

__global__ void weight_splat_kernel(const float* __restrict__ wgt) {
    for (int i = threadIdx.x; i < 1728; i += 256) {
        int co  = i / 216;  int rem = i - co * 216;
        int ci  = rem / 27; int r2  = rem - ci * 27;
        int kd  = r2 / 9;   int r3  = r2 - kd * 9;
        int kh  = r3 / 3;   int kw  = r3 - kh * 3;
        float w = wgt[i];
        gW_buf[((ci * 3 + kd) * 3 + kh) * 24 + kw * 8 + co] = pk2(w, w);
    }
}

// 12 packed FMAs: one output row, one kh, 2 couts, 2 pixel pairs
__device__ __forceinline__ void conv_out(u64* A, const ulonglong2& ca,
                                         const ulonglong2& sa, u64 r1,
                                         const ulonglong2& wL, const ulonglong2& wC,
                                         const ulonglong2& wR) {
    fma2(A[0], sa.x, wL.x);  fma2(A[1], sa.y, wL.x);
    fma2(A[0], ca.x, wC.x);  fma2(A[1], ca.y, wC.x);
    fma2(A[0], sa.y, wR.x);  fma2(A[1], r1,   wR.x);
    fma2(A[2], sa.x, wL.y);  fma2(A[3], sa.y, wL.y);
    fma2(A[2], ca.x, wC.y);  fma2(A[3], ca.y, wC.y);
    fma2(A[2], sa.y, wR.y);  fma2(A[3], r1,   wR.y);
}

__global__ void __launch_bounds__(128, 5)
conv3d_fused_kernel(const float* __restrict__ x,
                    const float* __restrict__ bias,
                    float* __restrict__ out)
{
    __shared__ __align__(16) float sC[NROWS * ROWP];   // 3 slices, x[r][w]
    __shared__ __align__(16) float sS[NROWS * ROWP];   // sS[r][k] = x[r][k-1]

    const int tid  = threadIdx.x;
    const int lane = tid & 31;
    const int warp = tid >> 5;          // 0..3 -> output row pair
    const int bx   = blockIdx.x;
    const int ht   = bx & 15;           // 16 H tiles of 8 rows
    const int dpos = (bx >> 4) & 31;
    const int b    = bx >> 9;
    const int h0   = ht << 3;

    // k=129 pads of the shifted copy (staging writes only k=0..128)
    if (tid < NROWS) sS[tid * ROWP + 129] = 0.0f;

    const int hr0 = warp << 1;   // first of 2 output rows within tile
    const int w0  = lane << 2;   // 4 pixels per thread

    u64 acc0[16], acc1[16];      // [cp2*4 + {coutA p0,p1, coutB p0,p1}]
    #pragma unroll
    for (int k = 0; k < 16; ++k) { acc0[k] = 0ull; acc1[k] = 0ull; }

    const int dlo = (dpos == 0)  ? 1 : 0;   // valid dz range (uniform)
    const int dhi = (dpos == 31) ? 2 : 3;

    for (int ci = 0; ci < 8; ++ci) {
        __syncthreads();   // previous ci's slabs fully consumed

        // --- stage all 3 slices (dpos-1 .. dpos+1), 30 rows x 128 cols ---
        // MLP capped at 4 in-flight LDG.128 (register budget for 5 CTAs/SM)
        const float4* xc4 = reinterpret_cast<const float4*>(x) +
                            ((size_t)(b * 8 + ci) << 17);   // *32*4096
        #pragma unroll 4
        for (int j = 0; j < 8; ++j) {
            int i = tid + j * 128;            // 0..1023, valid < 960
            if (i < 960) {
                int rowg = i >> 5;            // 0..29, uniform per warp
                int sz   = rowg / 10;         // slice (dz)
                int hz   = rowg - sz * 10;
                int dd   = dpos + sz - 1;
                int hg   = h0 + hz - 1;
                float4 v = make_float4(0.f, 0.f, 0.f, 0.f);
                if ((unsigned)dd < 32u && (unsigned)hg < 128u)
                    v = xc4[(dd << 12) + (hg << 5) + lane];
                float pw = __shfl_up_sync(0xffffffffu, v.w, 1);
                if (lane == 0) pw = 0.0f;     // x[-1] zero pad
                float* rowC = &sC[rowg * ROWP];
                float* rowS = &sS[rowg * ROWP];
                *reinterpret_cast<float4*>(rowC + (lane << 2)) = v;
                *reinterpret_cast<float4*>(rowS + (lane << 2)) =
                    make_float4(pw, v.x, v.y, v.z);
                if (lane == 31) rowS[128] = v.w;   // sS[128] = x[127]
            }
        }
        __syncthreads();

        // --- compute: 3 depth taps from the staged block ---
        #pragma unroll 1
        for (int dz = dlo; dz < dhi; ++dz) {
            const float* scb = &sC[dz * SLROWS * ROWP];
            const float* ssb = &sS[dz * SLROWS * ROWP];
            const u64* wbase = &cW[(ci * 3 + dz) * 72];

            ulonglong2 caA, saA, caB, saB;
            u64 r1A, r1B;
            {
                int off = hr0 * ROWP + w0;
                caA = *reinterpret_cast<const ulonglong2*>(&scb[off]);
                saA = *reinterpret_cast<const ulonglong2*>(&ssb[off]);
                r1A = *reinterpret_cast<const u64*>(&ssb[off + 4]);
                off += ROWP;
                caB = *reinterpret_cast<const ulonglong2*>(&scb[off]);
                saB = *reinterpret_cast<const ulonglong2*>(&ssb[off]);
                r1B = *reinterpret_cast<const u64*>(&ssb[off + 4]);
            }
            #pragma unroll
            for (int kh = 0; kh < 3; ++kh) {
                const u64* wp = wbase + kh * 24;
                #pragma unroll
                for (int cp2 = 0; cp2 < 4; ++cp2) {
                    ulonglong2 wL = *reinterpret_cast<const ulonglong2*>(wp + 2 * cp2);
                    ulonglong2 wC = *reinterpret_cast<const ulonglong2*>(wp + 8 + 2 * cp2);
                    ulonglong2 wR = *reinterpret_cast<const ulonglong2*>(wp + 16 + 2 * cp2);
                    conv_out(&acc0[cp2 * 4], caA, saA, r1A, wL, wC, wR);
                    conv_out(&acc1[cp2 * 4], caB, saB, r1B, wL, wC, wR);
                }
                if (kh < 2) {
                    caA = caB; saA = saB; r1A = r1B;    // renamed away by unroll
                    int off = (hr0 + kh + 2) * ROWP + w0;
                    caB = *reinterpret_cast<const ulonglong2*>(&scb[off]);
                    saB = *reinterpret_cast<const ulonglong2*>(&ssb[off]);
                    r1B = *reinterpret_cast<const u64*>(&ssb[off + 4]);
                }
            }
        }
    }

    // --- epilogue: activation chain + bias, vectorized coalesced stores ---
    #pragma unroll
    for (int co = 0; co < 8; ++co) {
        float bb = bias[co];
        const int cp2 = co >> 1, sub = (co & 1) * 2;
        const size_t cbase = ((size_t)((b * 8 + co) * 32 + dpos) << 14) + w0;
        #pragma unroll
        for (int o = 0; o < 2; ++o) {
            const u64* A = (o == 0) ? acc0 : acc1;
            float2 p0 = up2(A[cp2 * 4 + sub]);
            float2 p1 = up2(A[cp2 * 4 + sub + 1]);
            float4 r;
            r.x = act_chain(p0.x) + bb;
            r.y = act_chain(p0.y) + bb;
            r.z = act_chain(p1.x) + bb;
            r.w = act_chain(p1.y) + bb;
            *reinterpret_cast<float4*>(out + cbase + ((h0 + hr0 + o) << 7)) = r;
        }
    }
}

extern "C" void kernel_launch(void* const* d_in, const int* in_sizes, int n_in,
                              void* d_out, int out_size)
{
    const float* x    = (const float*)d_in[0];   // (8,8,32,128,128)
    const float* wgt  = (const float*)d_in[1];   // (8,8,3,3,3)
    const float* bias = (const float*)d_in[2];   // (8,1,1,1)
    float* out = (float*)d_out;                  // (8,8,32,128,128)

    weight_splat_kernel<<<1, 256>>>(wgt);
    void* gw_ptr = nullptr;
    cudaGetSymbolAddress(&gw_ptr, gW_buf);
    cudaMemcpyToSymbolAsync(cW, gw_ptr, 1728 * sizeof(u64), 0,
                            cudaMemcpyDeviceToDevice, 0);
    // grid = 16 H-tiles * 32 depths * 8 batches = 4096 blocks of 128 threads
    conv3d_fused_kernel<<<4096, 128>>>(x, bias, out);
}

// round 14
// speedup vs baseline: 1.6851x; 1.6851x over previous
#include <cuda_runtime.h>
#include <cuda_bf16.h>

// Fused Conv3d(8->8, k=3, same zero-pad) + sigmoid(gelu_tanh(relu(y))) + bias
// B=8, D=32, H=128, W=128. fp32, packed f32x2 FMAs.
//
// Round-14: warp-private pipeline, zero block barriers.
// Each warp owns 2 output rows; it stages its OWN 12 input rows (4 rows x 3
// depth slices) into a private SMEM strip (center copy + W-shifted copy) and
// computes from it. No __syncthreads in the main loop -- only __syncwarp().
// LDG waits of one warp are covered by the other 15 warps/SM (all staggered).
// GMEM volume x1.6 vs cooperative staging (adjacent warps re-read rows), but
// that's L2-hit traffic and DRAM stays ~18% of peak.
// Thread: 2 output rows x 4 W pixels x 8 couts (32 u64 accs). All f32x2
// operands are memory-aligned pairs. Weights in __constant__. 128 thr, 4 CTAs/SM.

#define SCSTR 128    // center-copy row stride (floats)
#define SSSTR 132    // shifted-copy row stride (floats; needs 130)
#define WROWS 12     // rows per warp strip (4 rows x 3 slices)
// per-warp floats: 12*128 + 12*132 = 3120 (12480 B); CTA: 4 warps = 49920 B
#define WARP_FLOATS (WROWS * SCSTR + WROWS * SSSTR)
#define SMEM_BYTES  (4 * WARP_FLOATS * 4)

typedef unsigned long long u64;

__constant__ __align__(16) u64 cW[1728];     // splatted (w,w), [(ci*3+kd)*3+kh][kw*8+co]
__device__   __align__(16) u64 gW_buf[1728];

__device__ __forceinline__ void fma2(u64& d, u64 a, u64 b) {
    asm("fma.rn.f32x2 %0, %1, %2, %0;" : "+l"(d) : "l"(a), "l"(b));
}
__device__ __forceinline__ u64 pk2(float lo, float hi) {
    u64 r;
    asm("mov.b64 %0, {%1, %2};" : "=l"(r) : "f"(lo), "f"(hi));
    return r;
}
__device__ __forceinline__ float2 up2(u64 v) {
    float lo, hi;
    asm("mov.b64 {%0, %1}, %2;" : "=f"(lo), "=f"(hi) : "l"(v));
    return make_float2(lo, hi);
}
__device__ __forceinline__ float tanhapx(float x) {
    float r;
    asm("tanh.approx.f32 %0, %1;" : "=f"(r) : "f"(x));
    return r;
}

// sigmoid(gelu_tanh(relu(y))) via 2x tanh.approx
__device__ __forceinline__ float act_chain(float y) {
    float yr = fmaxf(y, 0.0f);
    float q  = fmaf(0.044715f * yr, yr, 1.0f);
    float t  = 0.7978845608028654f * yr * q;
    float hyr = 0.5f * yr;
    float g  = fmaf(hyr, tanhapx(t), hyr);
    return fmaf(0.5f, tanhapx(0.5f * g), 0.5f);
}

__global__ void weight_splat_kernel(const float* __restrict__ wgt) {
    for (int i = threadIdx.x; i < 1728; i += 256) {
        int co  = i / 216;  int rem = i - co * 216;
        int ci  = rem / 27; int r2  = rem - ci * 27;
        int kd  = r2 / 9;   int r3  = r2 - kd * 9;
        int kh  = r3 / 3;   int kw  = r3 - kh * 3;
        float w = wgt[i];
        gW_buf[((ci * 3 + kd) * 3 + kh) * 24 + kw * 8 + co] = pk2(w, w);
    }
}

// 12 packed FMAs: one output row, one kh, 2 couts, 2 pixel pairs
__device__ __forceinline__ void conv_out(u64* A, const ulonglong2& ca,
                                         const ulonglong2& sa, u64 r1,
                                         const ulonglong2& wL, const ulonglong2& wC,
                                         const ulonglong2& wR) {
    fma2(A[0], sa.x, wL.x);  fma2(A[1], sa.y, wL.x);
    fma2(A[0], ca.x, wC.x);  fma2(A[1], ca.y, wC.x);
    fma2(A[0], sa.y, wR.x);  fma2(A[1], r1,   wR.x);
    fma2(A[2], sa.x, wL.y);  fma2(A[3], sa.y, wL.y);
    fma2(A[2], ca.x, wC.y);  fma2(A[3], ca.y, wC.y);
    fma2(A[2], sa.y, wR.y);  fma2(A[3], r1,   wR.y);
}

__global__ void __launch_bounds__(128, 4)
conv3d_fused_kernel(const float* __restrict__ x,
                    const float* __restrict__ bias,
                    float* __restrict__ out)
{
    extern __shared__ __align__(16) float smem[];

    const int tid  = threadIdx.x;
    const int lane = tid & 31;
    const int warp = tid >> 5;          // 0..3 -> output row pair
    const int bx   = blockIdx.x;
    const int ht   = bx & 15;           // 16 H tiles of 8 rows
    const int dpos = (bx >> 4) & 31;
    const int b    = bx >> 9;
    const int h0   = ht << 3;

    float* wsC = smem + warp * WARP_FLOATS;          // 12 rows x 128
    float* wsS = wsC + WROWS * SCSTR;                // 12 rows x 132

    // k=129 pad of each shifted row (staging writes only k=0..128)
    if (lane < WROWS) wsS[lane * SSSTR + 129] = 0.0f;

    const int hr0 = warp << 1;   // first of 2 output rows within tile
    const int w0  = lane << 2;   // 4 pixels per thread
    const int hgbase = h0 + hr0 - 1;

    u64 acc0[16], acc1[16];      // [cp2*4 + {coutA p0,p1, coutB p0,p1}]
    #pragma unroll
    for (int k = 0; k < 16; ++k) { acc0[k] = 0ull; acc1[k] = 0ull; }

    const int dlo = (dpos == 0)  ? 1 : 0;   // valid dz range (uniform)
    const int dhi = (dpos == 31) ? 2 : 3;

    for (int ci = 0; ci < 8; ++ci) {
        __syncwarp();   // strip fully consumed by this warp (WAR)

        // --- stage this warp's 12 rows (4 rows x 3 slices), both copies ---
        const float4* xc4 = reinterpret_cast<const float4*>(x) +
                            ((size_t)(b * 8 + ci) << 17);   // *32*4096
        #pragma unroll 4
        for (int r = 0; r < WROWS; ++r) {
            int sz = r >> 2;              // slice (dz)
            int rr = r & 3;               // row within window
            int dd = dpos + sz - 1;
            int hg = hgbase + rr;
            float4 v = make_float4(0.f, 0.f, 0.f, 0.f);
            if ((unsigned)dd < 32u && (unsigned)hg < 128u)
                v = xc4[(dd << 12) + (hg << 5) + lane];
            float pw = __shfl_up_sync(0xffffffffu, v.w, 1);
            if (lane == 0) pw = 0.0f;     // x[-1] zero pad
            *reinterpret_cast<float4*>(&wsC[r * SCSTR + w0]) = v;
            *reinterpret_cast<float4*>(&wsS[r * SSSTR + w0]) =
                make_float4(pw, v.x, v.y, v.z);
            if (lane == 31) wsS[r * SSSTR + 128] = v.w;   // sS[128] = x[127]
        }
        __syncwarp();   // cross-lane visibility of the strip

        // --- compute: 3 depth taps from the private strip ---
        #pragma unroll 1
        for (int dz = dlo; dz < dhi; ++dz) {
            const float* scb = wsC + dz * 4 * SCSTR;
            const float* ssb = wsS + dz * 4 * SSSTR;
            const u64* wbase = &cW[(ci * 3 + dz) * 72];

            ulonglong2 caA, saA, caB, saB;
            u64 r1A, r1B;
            caA = *reinterpret_cast<const ulonglong2*>(&scb[w0]);
            saA = *reinterpret_cast<const ulonglong2*>(&ssb[w0]);
            r1A = *reinterpret_cast<const u64*>(&ssb[w0 + 4]);
            caB = *reinterpret_cast<const ulonglong2*>(&scb[SCSTR + w0]);
            saB = *reinterpret_cast<const ulonglong2*>(&ssb[SSSTR + w0]);
            r1B = *reinterpret_cast<const u64*>(&ssb[SSSTR + w0 + 4]);

            #pragma unroll
            for (int kh = 0; kh < 3; ++kh) {
                const u64* wp = wbase + kh * 24;
                #pragma unroll
                for (int cp2 = 0; cp2 < 4; ++cp2) {
                    ulonglong2 wL = *reinterpret_cast<const ulonglong2*>(wp + 2 * cp2);
                    ulonglong2 wC = *reinterpret_cast<const ulonglong2*>(wp + 8 + 2 * cp2);
                    ulonglong2 wR = *reinterpret_cast<const ulonglong2*>(wp + 16 + 2 * cp2);
                    conv_out(&acc0[cp2 * 4], caA, saA, r1A, wL, wC, wR);
                    conv_out(&acc1[cp2 * 4], caB, saB, r1B, wL, wC, wR);
                }
                if (kh < 2) {
                    caA = caB; saA = saB; r1A = r1B;    // renamed away by unroll
                    int rc = (kh + 2) * SCSTR + w0;
                    int rs = (kh + 2) * SSSTR + w0;
                    caB = *reinterpret_cast<const ulonglong2*>(&scb[rc]);
                    saB = *reinterpret_cast<const ulonglong2*>(&ssb[rs]);
                    r1B = *reinterpret_cast<const u64*>(&ssb[rs + 4]);
                }
            }
        }
    }

    // --- epilogue: activation chain + bias, vectorized coalesced stores ---
    #pragma unroll
    for (int co = 0; co < 8; ++co) {
        float bb = bias[co];
        const int cp2 = co >> 1, sub = (co & 1) * 2;
        const size_t cbase = ((size_t)((b * 8 + co) * 32 + dpos) << 14) + w0;
        #pragma unroll
        for (int o = 0; o < 2; ++o) {
            const u64* A = (o == 0) ? acc0 : acc1;
            float2 p0 = up2(A[cp2 * 4 + sub]);
            float2 p1 = up2(A[cp2 * 4 + sub + 1]);
            float4 r;
            r.x = act_chain(p0.x) + bb;
            r.y = act_chain(p0.y) + bb;
            r.z = act_chain(p1.x) + bb;
            r.w = act_chain(p1.y) + bb;
            *reinterpret_cast<float4*>(out + cbase + ((h0 + hr0 + o) << 7)) = r;
        }
    }
}

extern "C" void kernel_launch(void* const* d_in, const int* in_sizes, int n_in,
                              void* d_out, int out_size)
{
    const float* x    = (const float*)d_in[0];   // (8,8,32,128,128)
    const float* wgt  = (const float*)d_in[1];   // (8,8,3,3,3)
    const float* bias = (const float*)d_in[2];   // (8,1,1,1)
    float* out = (float*)d_out;                  // (8,8,32,128,128)

    weight_splat_kernel<<<1, 256>>>(wgt);
    void* gw_ptr = nullptr;
    cudaGetSymbolAddress(&gw_ptr, gW_buf);
    cudaMemcpyToSymbolAsync(cW, gw_ptr, 1728 * sizeof(u64), 0,
                            cudaMemcpyDeviceToDevice, 0);

    static bool attr_set = false;
    if (!attr_set) {
        cudaFuncSetAttribute(conv3d_fused_kernel,
                             cudaFuncAttributeMaxDynamicSharedMemorySize, SMEM_BYTES);
        attr_set = true;
    }
    // grid = 16 H-tiles * 32 depths * 8 batches = 4096 blocks of 128 threads
    conv3d_fused_kernel<<<4096, 128, SMEM_BYTES>>>(x, bias, out);
}

// round 15
// speedup vs baseline: 1.7477x; 1.0371x over previous
#include <cuda_runtime.h>
#include <cuda_bf16.h>

// Fused Conv3d(8->8, k=3, same zero-pad) + sigmoid(gelu_tanh(relu(y))) + bias
// B=8, D=32, H=128, W=128. fp32, packed f32x2 FMAs.
//
// Round-15 = R11 (best: cp.async ci-granularity double-buffer, cooperative
// staging/sS build, one bar pair per ci) + STATIC fully-unrolled dz loop:
// out-of-range depth slices are zero-filled by cp.async (nbytes=0), so all
// CTAs compute all 3 taps (zero contribution at boundaries) and ptxas can
// software-pipeline loads across dz boundaries. dlo/dhi logic removed.
// Thread: 2 output H rows x 4 W pixels x 8 couts (32 u64 accs). All f32x2
// operands are memory-aligned pairs. Weights in __constant__. 128thr, 4 CTA/SM.

#define ROWP 132     // padded row stride in floats
#define SLROWS 10    // rows per staged slice
#define NROWS 30     // 3 slices

typedef unsigned long long u64;

__constant__ __align__(16) u64 cW[1728];     // splatted (w,w), [(ci*3+kd)*3+kh][kw*8+co]
__device__   __align__(16) u64 gW_buf[1728];

__device__ __forceinline__ void fma2(u64& d, u64 a, u64 b) {
    asm("fma.rn.f32x2 %0, %1, %2, %0;" : "+l"(d) : "l"(a), "l"(b));
}
__device__ __forceinline__ u64 pk2(float lo, float hi) {
    u64 r;
    asm("mov.b64 %0, {%1, %2};" : "=l"(r) : "f"(lo), "f"(hi));
    return r;
}
__device__ __forceinline__ float2 up2(u64 v) {
    float lo, hi;
    asm("mov.b64 {%0, %1}, %2;" : "=f"(lo), "=f"(hi) : "l"(v));
    return make_float2(lo, hi);
}
__device__ __forceinline__ float tanhapx(float x) {
    float r;
    asm("tanh.approx.f32 %0, %1;" : "=f"(r) : "f"(x));
    return r;
}

// sigmoid(gelu_tanh(relu(y))) via 2x tanh.approx
__device__ __forceinline__ float act_chain(float y) {
    float yr = fmaxf(y, 0.0f);
    float q  = fmaf(0.044715f * yr, yr, 1.0f);
    float t  = 0.7978845608028654f * yr * q;
    float hyr = 0.5f * yr;
    float g  = fmaf(hyr, tanhapx(t), hyr);
    return fmaf(0.5f, tanhapx(0.5f * g), 0.5f);
}

__global__ void weight_splat_kernel(const float* __restrict__ wgt) {
    for (int i = threadIdx.x; i < 1728; i += 256) {
        int co  = i / 216;  int rem = i - co * 216;
        int ci  = rem / 27; int r2  = rem - ci * 27;
        int kd  = r2 / 9;   int r3  = r2 - kd * 9;
        int kh  = r3 / 3;   int kw  = r3 - kh * 3;
        float w = wgt[i];
        gW_buf[((ci * 3 + kd) * 3 + kh) * 24 + kw * 8 + co] = pk2(w, w);
    }
}

// issue cp.async fill of one 30x128 block (3 slices of cin ci) into dst
// out-of-range (D/H pad) rows are zero-filled (nbytes=0)
__device__ __forceinline__ void stage_issue(float* dst, const float* __restrict__ x,
                                            int b, int ci, int dpos, int h0,
                                            int tid, int lane) {
    const float4* xc4 = reinterpret_cast<const float4*>(x) +
                        ((size_t)(b * 8 + ci) << 17);   // * 32 * 4096
    #pragma unroll
    for (int j = 0; j < 8; ++j) {
        int i = tid + j * 128;                // 0..1023, valid < 960
        if (i < 960) {
            int rowg = i >> 5;                // 0..29
            int sz   = rowg / 10;
            int hz   = rowg - sz * 10;
            int dd   = dpos + sz - 1;
            int hg   = h0 + hz - 1;
            bool ok = ((unsigned)dd < 32u) && ((unsigned)hg < 128u);
            const float4* src = xc4 + (((ok ? dd : 0) << 12) + ((ok ? hg : 0) << 5) + lane);
            unsigned d = (unsigned)__cvta_generic_to_shared(dst + rowg * ROWP + (lane << 2));
            int nbytes = ok ? 16 : 0;         // 0 => zero-fill (D/H pad)
            asm volatile("cp.async.cg.shared.global [%0], [%1], 16, %2;"
                         :: "r"(d), "l"(src), "r"(nbytes));
        }
    }
    asm volatile("cp.async.commit_group;");
}

// 12 packed FMAs: one output row, one kh, 2 couts, 2 pixel pairs
__device__ __forceinline__ void conv_out(u64* A, const ulonglong2& ca,
                                         const ulonglong2& sa, u64 r1,
                                         const ulonglong2& wL, const ulonglong2& wC,
                                         const ulonglong2& wR) {
    fma2(A[0], sa.x, wL.x);  fma2(A[1], sa.y, wL.x);
    fma2(A[0], ca.x, wC.x);  fma2(A[1], ca.y, wC.x);
    fma2(A[0], sa.y, wR.x);  fma2(A[1], r1,   wR.x);
    fma2(A[2], sa.x, wL.y);  fma2(A[3], sa.y, wL.y);
    fma2(A[2], ca.x, wC.y);  fma2(A[3], ca.y, wC.y);
    fma2(A[2], sa.y, wR.y);  fma2(A[3], r1,   wR.y);
}

__global__ void __launch_bounds__(128, 4)
conv3d_fused_kernel(const float* __restrict__ x,
                    const float* __restrict__ bias,
                    float* __restrict__ out)
{
    __shared__ __align__(16) float sC[2][NROWS * ROWP];  // ping-pong, x[r][w]
    __shared__ __align__(16) float sS[NROWS * ROWP];     // sS[r][k] = x[r][k-1]

    const int tid  = threadIdx.x;
    const int lane = tid & 31;
    const int warp = tid >> 5;
    const int bx   = blockIdx.x;
    const int ht   = bx & 15;
    const int dpos = (bx >> 4) & 31;
    const int b    = bx >> 9;
    const int h0   = ht << 3;

    // k=129 pads of sS (build pass writes only k=0..128)
    if (tid < NROWS) sS[tid * ROWP + 129] = 0.0f;

    const int hr0 = warp << 1;   // first of 2 output rows within tile
    const int w0  = lane << 2;   // 4 pixels per thread

    u64 acc0[16], acc1[16];
    #pragma unroll
    for (int k = 0; k < 16; ++k) { acc0[k] = 0ull; acc1[k] = 0ull; }

    // prologue: fill buffer 0 with ci=0
    stage_issue(sC[0], x, b, 0, dpos, h0, tid, lane);

    for (int ci = 0; ci < 8; ++ci) {
        const int p = ci & 1;
        const float* scfull = sC[p];

        asm volatile("cp.async.wait_group 0;");   // ci's block landed
        __syncthreads();                          // + prev compute done (sS free)

        // prefetch ci+1 into the other buffer (overlaps sS build + compute)
        if (ci < 7)
            stage_issue(sC[1 - p], x, b, ci + 1, dpos, h0, tid, lane);

        // build sS[r][k+1] = scfull[r][k] (30 rows, 4 warps, cooperative)
        #pragma unroll
        for (int j = 0; j < 8; ++j) {
            int row = warp + (j << 2);            // 0..31, valid < 30
            if (row < NROWS) {
                float4 v = *reinterpret_cast<const float4*>(
                    &scfull[row * ROWP + (lane << 2)]);
                float pw = __shfl_up_sync(0xffffffffu, v.w, 1);
                if (lane == 0) pw = 0.0f;         // x[-1] zero pad
                *reinterpret_cast<float4*>(&sS[row * ROWP + (lane << 2)]) =
                    make_float4(pw, v.x, v.y, v.z);
                if (lane == 31) sS[row * ROWP + 128] = v.w;
            }
        }
        __syncthreads();

        // compute: 3 depth taps, STATIC fully-unrolled (zero-filled pads make
        // boundary taps contribute exactly zero)
        #pragma unroll
        for (int dz = 0; dz < 3; ++dz) {
            const float* scb = &scfull[dz * SLROWS * ROWP];
            const float* ssb = &sS[dz * SLROWS * ROWP];
            const u64* wbase = &cW[(ci * 3 + dz) * 72];

            ulonglong2 caA, saA, caB, saB;
            u64 r1A, r1B;
            {
                int off = hr0 * ROWP + w0;
                caA = *reinterpret_cast<const ulonglong2*>(&scb[off]);
                saA = *reinterpret_cast<const ulonglong2*>(&ssb[off]);
                r1A = *reinterpret_cast<const u64*>(&ssb[off + 4]);
                off += ROWP;
                caB = *reinterpret_cast<const ulonglong2*>(&scb[off]);
                saB = *reinterpret_cast<const ulonglong2*>(&ssb[off]);
                r1B = *reinterpret_cast<const u64*>(&ssb[off + 4]);
            }
            #pragma unroll
            for (int kh = 0; kh < 3; ++kh) {
                const u64* wp = wbase + kh * 24;
                #pragma unroll
                for (int cp2 = 0; cp2 < 4; ++cp2) {
                    ulonglong2 wL = *reinterpret_cast<const ulonglong2*>(wp + 2 * cp2);
                    ulonglong2 wC = *reinterpret_cast<const ulonglong2*>(wp + 8 + 2 * cp2);
                    ulonglong2 wR = *reinterpret_cast<const ulonglong2*>(wp + 16 + 2 * cp2);
                    conv_out(&acc0[cp2 * 4], caA, saA, r1A, wL, wC, wR);
                    conv_out(&acc1[cp2 * 4], caB, saB, r1B, wL, wC, wR);
                }
                if (kh < 2) {
                    caA = caB; saA = saB; r1A = r1B;    // renamed away by unroll
                    int off = (hr0 + kh + 2) * ROWP + w0;
                    caB = *reinterpret_cast<const ulonglong2*>(&scb[off]);
                    saB = *reinterpret_cast<const ulonglong2*>(&ssb[off]);
                    r1B = *reinterpret_cast<const u64*>(&ssb[off + 4]);
                }
            }
        }
    }

    // --- epilogue: activation chain + bias, vectorized coalesced stores ---
    #pragma unroll
    for (int co = 0; co < 8; ++co) {
        float bb = bias[co];
        const int cp2 = co >> 1, sub = (co & 1) * 2;
        const size_t cbase = ((size_t)((b * 8 + co) * 32 + dpos) << 14) + w0;
        #pragma unroll
        for (int o = 0; o < 2; ++o) {
            const u64* A = (o == 0) ? acc0 : acc1;
            float2 p0 = up2(A[cp2 * 4 + sub]);
            float2 p1 = up2(A[cp2 * 4 + sub + 1]);
            float4 r;
            r.x = act_chain(p0.x) + bb;
            r.y = act_chain(p0.y) + bb;
            r.z = act_chain(p1.x) + bb;
            r.w = act_chain(p1.y) + bb;
            *reinterpret_cast<float4*>(out + cbase + ((h0 + hr0 + o) << 7)) = r;
        }
    }
}

extern "C" void kernel_launch(void* const* d_in, const int* in_sizes, int n_in,
                              void* d_out, int out_size)
{
    const float* x    = (const float*)d_in[0];   // (8,8,32,128,128)
    const float* wgt  = (const float*)d_in[1];   // (8,8,3,3,3)
    const float* bias = (const float*)d_in[2];   // (8,1,1,1)
    float* out = (float*)d_out;                  // (8,8,32,128,128)

    weight_splat_kernel<<<1, 256>>>(wgt);
    void* gw_ptr = nullptr;
    cudaGetSymbolAddress(&gw_ptr, gW_buf);
    cudaMemcpyToSymbolAsync(cW, gw_ptr, 1728 * sizeof(u64), 0,
                            cudaMemcpyDeviceToDevice, 0);
    // grid = 16 H-tiles * 32 depths * 8 batches = 4096 blocks of 128 threads
    conv3d_fused_kernel<<<4096, 128>>>(x, bias, out);
}

// round 16
// speedup vs baseline: 1.7764x; 1.0164x over previous
#include <cuda_runtime.h>
#include <cuda_bf16.h>

// Fused Conv3d(8->8, k=3, same zero-pad) + sigmoid(gelu_tanh(relu(y))) + bias
// B=8, D=32, H=128, W=128. fp32, packed f32x2 FMAs.
//
// Round-16 = R15 (static dz unroll, cp.async ci double-buffer, cooperative
// sS build, const weights) + latency trims:
//  - per-ci phase order: bar -> build sS -> issue prefetch -> compute
//    (prefetch LDGSTS no longer delays the build chain gating compute)
//  - sS build processes 2 rows per step (paired LDS/shfl/STS for MLP).
// Thread: 2 output H rows x 4 W pixels x 8 couts (32 u64 accs). All f32x2
// operands are memory-aligned pairs. 128 thr, 4 CTAs/SM.

#define ROWP 132     // padded row stride in floats
#define SLROWS 10    // rows per staged slice
#define NROWS 30     // 3 slices

typedef unsigned long long u64;

__constant__ __align__(16) u64 cW[1728];     // splatted (w,w), [(ci*3+kd)*3+kh][kw*8+co]
__device__   __align__(16) u64 gW_buf[1728];

__device__ __forceinline__ void fma2(u64& d, u64 a, u64 b) {
    asm("fma.rn.f32x2 %0, %1, %2, %0;" : "+l"(d) : "l"(a), "l"(b));
}
__device__ __forceinline__ u64 pk2(float lo, float hi) {
    u64 r;
    asm("mov.b64 %0, {%1, %2};" : "=l"(r) : "f"(lo), "f"(hi));
    return r;
}
__device__ __forceinline__ float2 up2(u64 v) {
    float lo, hi;
    asm("mov.b64 {%0, %1}, %2;" : "=f"(lo), "=f"(hi) : "l"(v));
    return make_float2(lo, hi);
}
__device__ __forceinline__ float tanhapx(float x) {
    float r;
    asm("tanh.approx.f32 %0, %1;" : "=f"(r) : "f"(x));
    return r;
}

// sigmoid(gelu_tanh(relu(y))) via 2x tanh.approx
__device__ __forceinline__ float act_chain(float y) {
    float yr = fmaxf(y, 0.0f);
    float q  = fmaf(0.044715f * yr, yr, 1.0f);
    float t  = 0.7978845608028654f * yr * q;
    float hyr = 0.5f * yr;
    float g  = fmaf(hyr, tanhapx(t), hyr);
    return fmaf(0.5f, tanhapx(0.5f * g), 0.5f);
}

__global__ void weight_splat_kernel(const float* __restrict__ wgt) {
    for (int i = threadIdx.x; i < 1728; i += 256) {
        int co  = i / 216;  int rem = i - co * 216;
        int ci  = rem / 27; int r2  = rem - ci * 27;
        int kd  = r2 / 9;   int r3  = r2 - kd * 9;
        int kh  = r3 / 3;   int kw  = r3 - kh * 3;
        float w = wgt[i];
        gW_buf[((ci * 3 + kd) * 3 + kh) * 24 + kw * 8 + co] = pk2(w, w);
    }
}

// issue cp.async fill of one 30x128 block (3 slices of cin ci) into dst;
// out-of-range (D/H pad) rows are zero-filled (nbytes=0)
__device__ __forceinline__ void stage_issue(float* dst, const float* __restrict__ x,
                                            int b, int ci, int dpos, int h0,
                                            int tid, int lane) {
    const float4* xc4 = reinterpret_cast<const float4*>(x) +
                        ((size_t)(b * 8 + ci) << 17);   // * 32 * 4096
    #pragma unroll
    for (int j = 0; j < 8; ++j) {
        int i = tid + j * 128;                // 0..1023, valid < 960
        if (i < 960) {
            int rowg = i >> 5;                // 0..29
            int sz   = rowg / 10;
            int hz   = rowg - sz * 10;
            int dd   = dpos + sz - 1;
            int hg   = h0 + hz - 1;
            bool ok = ((unsigned)dd < 32u) && ((unsigned)hg < 128u);
            const float4* src = xc4 + (((ok ? dd : 0) << 12) + ((ok ? hg : 0) << 5) + lane);
            unsigned d = (unsigned)__cvta_generic_to_shared(dst + rowg * ROWP + (lane << 2));
            int nbytes = ok ? 16 : 0;         // 0 => zero-fill (D/H pad)
            asm volatile("cp.async.cg.shared.global [%0], [%1], 16, %2;"
                         :: "r"(d), "l"(src), "r"(nbytes));
        }
    }
    asm volatile("cp.async.commit_group;");
}

// 12 packed FMAs: one output row, one kh, 2 couts, 2 pixel pairs
__device__ __forceinline__ void conv_out(u64* A, const ulonglong2& ca,
                                         const ulonglong2& sa, u64 r1,
                                         const ulonglong2& wL, const ulonglong2& wC,
                                         const ulonglong2& wR) {
    fma2(A[0], sa.x, wL.x);  fma2(A[1], sa.y, wL.x);
    fma2(A[0], ca.x, wC.x);  fma2(A[1], ca.y, wC.x);
    fma2(A[0], sa.y, wR.x);  fma2(A[1], r1,   wR.x);
    fma2(A[2], sa.x, wL.y);  fma2(A[3], sa.y, wL.y);
    fma2(A[2], ca.x, wC.y);  fma2(A[3], ca.y, wC.y);
    fma2(A[2], sa.y, wR.y);  fma2(A[3], r1,   wR.y);
}

__global__ void __launch_bounds__(128, 4)
conv3d_fused_kernel(const float* __restrict__ x,
                    const float* __restrict__ bias,
                    float* __restrict__ out)
{
    __shared__ __align__(16) float sC[2][NROWS * ROWP];  // ping-pong, x[r][w]
    __shared__ __align__(16) float sS[NROWS * ROWP];     // sS[r][k] = x[r][k-1]

    const int tid  = threadIdx.x;
    const int lane = tid & 31;
    const int warp = tid >> 5;
    const int bx   = blockIdx.x;
    const int ht   = bx & 15;
    const int dpos = (bx >> 4) & 31;
    const int b    = bx >> 9;
    const int h0   = ht << 3;

    // k=129 pads of sS (build pass writes only k=0..128)
    if (tid < NROWS) sS[tid * ROWP + 129] = 0.0f;

    const int hr0 = warp << 1;   // first of 2 output rows within tile
    const int w0  = lane << 2;   // 4 pixels per thread

    u64 acc0[16], acc1[16];
    #pragma unroll
    for (int k = 0; k < 16; ++k) { acc0[k] = 0ull; acc1[k] = 0ull; }

    // prologue: fill buffer 0 with ci=0
    stage_issue(sC[0], x, b, 0, dpos, h0, tid, lane);

    for (int ci = 0; ci < 8; ++ci) {
        const int p = ci & 1;
        const float* scfull = sC[p];

        asm volatile("cp.async.wait_group 0;");   // ci's block landed
        __syncthreads();                          // + prev compute done (sS free)

        // build sS[r][k+1] = scfull[r][k]; 2 rows per step for load MLP.
        // rows handled: warp, warp+4, ..., warp+28 (cooperative, no dup)
        #pragma unroll
        for (int j = 0; j < 4; ++j) {
            int rA = warp + (j << 3);             // warp + 8j      (0..27)
            int rB = rA + 4;                      // warp + 8j + 4  (4..31)
            float4 vA = *reinterpret_cast<const float4*>(
                &scfull[rA * ROWP + (lane << 2)]);
            float4 vB;
            bool okB = rB < NROWS;
            if (okB) vB = *reinterpret_cast<const float4*>(
                &scfull[rB * ROWP + (lane << 2)]);
            float pwA = __shfl_up_sync(0xffffffffu, vA.w, 1);
            float pwB = okB ? __shfl_up_sync(0xffffffffu, vB.w, 1) : 0.f;
            if (lane == 0) { pwA = 0.0f; pwB = 0.0f; }
            *reinterpret_cast<float4*>(&sS[rA * ROWP + (lane << 2)]) =
                make_float4(pwA, vA.x, vA.y, vA.z);
            if (lane == 31) sS[rA * ROWP + 128] = vA.w;
            if (okB) {
                *reinterpret_cast<float4*>(&sS[rB * ROWP + (lane << 2)]) =
                    make_float4(pwB, vB.x, vB.y, vB.z);
                if (lane == 31) sS[rB * ROWP + 128] = vB.w;
            }
        }

        // prefetch ci+1 AFTER the build chain (doesn't gate compute start;
        // still lands within ci's full compute window)
        if (ci < 7)
            stage_issue(sC[1 - p], x, b, ci + 1, dpos, h0, tid, lane);

        __syncthreads();

        // compute: 3 depth taps, static fully-unrolled (zero-filled pads)
        #pragma unroll
        for (int dz = 0; dz < 3; ++dz) {
            const float* scb = &scfull[dz * SLROWS * ROWP];
            const float* ssb = &sS[dz * SLROWS * ROWP];
            const u64* wbase = &cW[(ci * 3 + dz) * 72];

            ulonglong2 caA, saA, caB, saB;
            u64 r1A, r1B;
            {
                int off = hr0 * ROWP + w0;
                caA = *reinterpret_cast<const ulonglong2*>(&scb[off]);
                saA = *reinterpret_cast<const ulonglong2*>(&ssb[off]);
                r1A = *reinterpret_cast<const u64*>(&ssb[off + 4]);
                off += ROWP;
                caB = *reinterpret_cast<const ulonglong2*>(&scb[off]);
                saB = *reinterpret_cast<const ulonglong2*>(&ssb[off]);
                r1B = *reinterpret_cast<const u64*>(&ssb[off + 4]);
            }
            #pragma unroll
            for (int kh = 0; kh < 3; ++kh) {
                const u64* wp = wbase + kh * 24;
                #pragma unroll
                for (int cp2 = 0; cp2 < 4; ++cp2) {
                    ulonglong2 wL = *reinterpret_cast<const ulonglong2*>(wp + 2 * cp2);
                    ulonglong2 wC = *reinterpret_cast<const ulonglong2*>(wp + 8 + 2 * cp2);
                    ulonglong2 wR = *reinterpret_cast<const ulonglong2*>(wp + 16 + 2 * cp2);
                    conv_out(&acc0[cp2 * 4], caA, saA, r1A, wL, wC, wR);
                    conv_out(&acc1[cp2 * 4], caB, saB, r1B, wL, wC, wR);
                }
                if (kh < 2) {
                    caA = caB; saA = saB; r1A = r1B;    // renamed away by unroll
                    int off = (hr0 + kh + 2) * ROWP + w0;
                    caB = *reinterpret_cast<const ulonglong2*>(&scb[off]);
                    saB = *reinterpret_cast<const ulonglong2*>(&ssb[off]);
                    r1B = *reinterpret_cast<const u64*>(&ssb[off + 4]);
                }
            }
        }
    }

    // --- epilogue: activation chain + bias, vectorized coalesced stores ---
    #pragma unroll
    for (int co = 0; co < 8; ++co) {
        float bb = bias[co];
        const int cp2 = co >> 1, sub = (co & 1) * 2;
        const size_t cbase = ((size_t)((b * 8 + co) * 32 + dpos) << 14) + w0;
        #pragma unroll
        for (int o = 0; o < 2; ++o) {
            const u64* A = (o == 0) ? acc0 : acc1;
            float2 p0 = up2(A[cp2 * 4 + sub]);
            float2 p1 = up2(A[cp2 * 4 + sub + 1]);
            float4 r;
            r.x = act_chain(p0.x) + bb;
            r.y = act_chain(p0.y) + bb;
            r.z = act_chain(p1.x) + bb;
            r.w = act_chain(p1.y) + bb;
            *reinterpret_cast<float4*>(out + cbase + ((h0 + hr0 + o) << 7)) = r;
        }
    }
}

extern "C" void kernel_launch(void* const* d_in, const int* in_sizes, int n_in,
                              void* d_out, int out_size)
{
    const float* x    = (const float*)d_in[0];   // (8,8,32,128,128)
    const float* wgt  = (const float*)d_in[1];   // (8,8,3,3,3)
    const float* bias = (const float*)d_in[2];   // (8,1,1,1)
    float* out = (float*)d_out;                  // (8,8,32,128,128)

    weight_splat_kernel<<<1, 256>>>(wgt);
    void* gw_ptr = nullptr;
    cudaGetSymbolAddress(&gw_ptr, gW_buf);
    cudaMemcpyToSymbolAsync(cW, gw_ptr, 1728 * sizeof(u64), 0,
                            cudaMemcpyDeviceToDevice, 0);
    // grid = 16 H-tiles * 32 depths * 8 batches = 4096 blocks of 128 threads
    conv3d_fused_kernel<<<4096, 128>>>(x, bias, out);
}

// round 17
// speedup vs baseline: 1.7869x; 1.0059x over previous
#include <cuda_runtime.h>
#include <cuda_bf16.h>

// Fused Conv3d(8->8, k=3, same zero-pad) + sigmoid(gelu_tanh(relu(y))) + bias
// B=8, D=32, H=128, W=128. fp32, packed f32x2 FMAs.
//
// Round-17 = R16 + L2-locality grid order: dpos is the FASTEST-varying
// block-index digit, so co-resident CTAs span adjacent depths of the same
// (b, H-tile) and share 2/3 of their staged input slices in L2 (cp.async
// fills become mostly L2 hits; lower DRAM traffic, tighter fill latency).
// Everything else identical to R16:
//  - cp.async ci-granularity double-buffer, static 3-tap dz unroll
//    (boundary slices zero-filled), cooperative paired sS build,
//    phase order: wait -> bar -> build -> prefetch -> bar -> compute
//  - weights in __constant__; all f32x2 operands memory-aligned pairs
//  - thread: 2 output H rows x 4 W pixels x 8 couts; 128 thr, 4 CTAs/SM.

#define ROWP 132     // padded row stride in floats
#define SLROWS 10    // rows per staged slice
#define NROWS 30     // 3 slices

typedef unsigned long long u64;

__constant__ __align__(16) u64 cW[1728];     // splatted (w,w), [(ci*3+kd)*3+kh][kw*8+co]
__device__   __align__(16) u64 gW_buf[1728];

__device__ __forceinline__ void fma2(u64& d, u64 a, u64 b) {
    asm("fma.rn.f32x2 %0, %1, %2, %0;" : "+l"(d) : "l"(a), "l"(b));
}
__device__ __forceinline__ u64 pk2(float lo, float hi) {
    u64 r;
    asm("mov.b64 %0, {%1, %2};" : "=l"(r) : "f"(lo), "f"(hi));
    return r;
}
__device__ __forceinline__ float2 up2(u64 v) {
    float lo, hi;
    asm("mov.b64 {%0, %1}, %2;" : "=f"(lo), "=f"(hi) : "l"(v));
    return make_float2(lo, hi);
}
__device__ __forceinline__ float tanhapx(float x) {
    float r;
    asm("tanh.approx.f32 %0, %1;" : "=f"(r) : "f"(x));
    return r;
}

// sigmoid(gelu_tanh(relu(y))) via 2x tanh.approx
__device__ __forceinline__ float act_chain(float y) {
    float yr = fmaxf(y, 0.0f);
    float q  = fmaf(0.044715f * yr, yr, 1.0f);
    float t  = 0.7978845608028654f * yr * q;
    float hyr = 0.5f * yr;
    float g  = fmaf(hyr, tanhapx(t), hyr);
    return fmaf(0.5f, tanhapx(0.5f * g), 0.5f);
}

__global__ void weight_splat_kernel(const float* __restrict__ wgt) {
    for (int i = threadIdx.x; i < 1728; i += 256) {
        int co  = i / 216;  int rem = i - co * 216;
        int ci  = rem / 27; int r2  = rem - ci * 27;
        int kd  = r2 / 9;   int r3  = r2 - kd * 9;
        int kh  = r3 / 3;   int kw  = r3 - kh * 3;
        float w = wgt[i];
        gW_buf[((ci * 3 + kd) * 3 + kh) * 24 + kw * 8 + co] = pk2(w, w);
    }
}

// issue cp.async fill of one 30x128 block (3 slices of cin ci) into dst;
// out-of-range (D/H pad) rows are zero-filled (nbytes=0)
__device__ __forceinline__ void stage_issue(float* dst, const float* __restrict__ x,
                                            int b, int ci, int dpos, int h0,
                                            int tid, int lane) {
    const float4* xc4 = reinterpret_cast<const float4*>(x) +
                        ((size_t)(b * 8 + ci) << 17);   // * 32 * 4096
    #pragma unroll
    for (int j = 0; j < 8; ++j) {
        int i = tid + j * 128;                // 0..1023, valid < 960
        if (i < 960) {
            int rowg = i >> 5;                // 0..29
            int sz   = rowg / 10;
            int hz   = rowg - sz * 10;
            int dd   = dpos + sz - 1;
            int hg   = h0 + hz - 1;
            bool ok = ((unsigned)dd < 32u) && ((unsigned)hg < 128u);
            const float4* src = xc4 + (((ok ? dd : 0) << 12) + ((ok ? hg : 0) << 5) + lane);
            unsigned d = (unsigned)__cvta_generic_to_shared(dst + rowg * ROWP + (lane << 2));
            int nbytes = ok ? 16 : 0;         // 0 => zero-fill (D/H pad)
            asm volatile("cp.async.cg.shared.global [%0], [%1], 16, %2;"
                         :: "r"(d), "l"(src), "r"(nbytes));
        }
    }
    asm volatile("cp.async.commit_group;");
}

// 12 packed FMAs: one output row, one kh, 2 couts, 2 pixel pairs
__device__ __forceinline__ void conv_out(u64* A, const ulonglong2& ca,
                                         const ulonglong2& sa, u64 r1,
                                         const ulonglong2& wL, const ulonglong2& wC,
                                         const ulonglong2& wR) {
    fma2(A[0], sa.x, wL.x);  fma2(A[1], sa.y, wL.x);
    fma2(A[0], ca.x, wC.x);  fma2(A[1], ca.y, wC.x);
    fma2(A[0], sa.y, wR.x);  fma2(A[1], r1,   wR.x);
    fma2(A[2], sa.x, wL.y);  fma2(A[3], sa.y, wL.y);
    fma2(A[2], ca.x, wC.y);  fma2(A[3], ca.y, wC.y);
    fma2(A[2], sa.y, wR.y);  fma2(A[3], r1,   wR.y);
}

__global__ void __launch_bounds__(128, 4)
conv3d_fused_kernel(const float* __restrict__ x,
                    const float* __restrict__ bias,
                    float* __restrict__ out)
{
    __shared__ __align__(16) float sC[2][NROWS * ROWP];  // ping-pong, x[r][w]
    __shared__ __align__(16) float sS[NROWS * ROWP];     // sS[r][k] = x[r][k-1]

    const int tid  = threadIdx.x;
    const int lane = tid & 31;
    const int warp = tid >> 5;
    const int bx   = blockIdx.x;
    // dpos fastest: co-resident CTAs span adjacent depths (share staged slices in L2)
    const int dpos = bx & 31;
    const int ht   = (bx >> 5) & 15;
    const int b    = bx >> 9;
    const int h0   = ht << 3;

    // k=129 pads of sS (build pass writes only k=0..128)
    if (tid < NROWS) sS[tid * ROWP + 129] = 0.0f;

    const int hr0 = warp << 1;   // first of 2 output rows within tile
    const int w0  = lane << 2;   // 4 pixels per thread

    u64 acc0[16], acc1[16];
    #pragma unroll
    for (int k = 0; k < 16; ++k) { acc0[k] = 0ull; acc1[k] = 0ull; }

    // prologue: fill buffer 0 with ci=0
    stage_issue(sC[0], x, b, 0, dpos, h0, tid, lane);

    for (int ci = 0; ci < 8; ++ci) {
        const int p = ci & 1;
        const float* scfull = sC[p];

        asm volatile("cp.async.wait_group 0;");   // ci's block landed
        __syncthreads();                          // + prev compute done (sS free)

        // build sS[r][k+1] = scfull[r][k]; 2 rows per step for load MLP.
        // rows handled: warp, warp+4, ..., warp+28 (cooperative, no dup)
        #pragma unroll
        for (int j = 0; j < 4; ++j) {
            int rA = warp + (j << 3);             // warp + 8j      (0..27)
            int rB = rA + 4;                      // warp + 8j + 4  (4..31)
            float4 vA = *reinterpret_cast<const float4*>(
                &scfull[rA * ROWP + (lane << 2)]);
            float4 vB;
            bool okB = rB < NROWS;
            if (okB) vB = *reinterpret_cast<const float4*>(
                &scfull[rB * ROWP + (lane << 2)]);
            float pwA = __shfl_up_sync(0xffffffffu, vA.w, 1);
            float pwB = okB ? __shfl_up_sync(0xffffffffu, vB.w, 1) : 0.f;
            if (lane == 0) { pwA = 0.0f; pwB = 0.0f; }
            *reinterpret_cast<float4*>(&sS[rA * ROWP + (lane << 2)]) =
                make_float4(pwA, vA.x, vA.y, vA.z);
            if (lane == 31) sS[rA * ROWP + 128] = vA.w;
            if (okB) {
                *reinterpret_cast<float4*>(&sS[rB * ROWP + (lane << 2)]) =
                    make_float4(pwB, vB.x, vB.y, vB.z);
                if (lane == 31) sS[rB * ROWP + 128] = vB.w;
            }
        }

        // prefetch ci+1 AFTER the build chain (doesn't gate compute start)
        if (ci < 7)
            stage_issue(sC[1 - p], x, b, ci + 1, dpos, h0, tid, lane);

        __syncthreads();

        // compute: 3 depth taps, static fully-unrolled (zero-filled pads)
        #pragma unroll
        for (int dz = 0; dz < 3; ++dz) {
            const float* scb = &scfull[dz * SLROWS * ROWP];
            const float* ssb = &sS[dz * SLROWS * ROWP];
            const u64* wbase = &cW[(ci * 3 + dz) * 72];

            ulonglong2 caA, saA, caB, saB;
            u64 r1A, r1B;
            {
                int off = hr0 * ROWP + w0;
                caA = *reinterpret_cast<const ulonglong2*>(&scb[off]);
                saA = *reinterpret_cast<const ulonglong2*>(&ssb[off]);
                r1A = *reinterpret_cast<const u64*>(&ssb[off + 4]);
                off += ROWP;
                caB = *reinterpret_cast<const ulonglong2*>(&scb[off]);
                saB = *reinterpret_cast<const ulonglong2*>(&ssb[off]);
                r1B = *reinterpret_cast<const u64*>(&ssb[off + 4]);
            }
            #pragma unroll
            for (int kh = 0; kh < 3; ++kh) {
                const u64* wp = wbase + kh * 24;
                #pragma unroll
                for (int cp2 = 0; cp2 < 4; ++cp2) {
                    ulonglong2 wL = *reinterpret_cast<const ulonglong2*>(wp + 2 * cp2);
                    ulonglong2 wC = *reinterpret_cast<const ulonglong2*>(wp + 8 + 2 * cp2);
                    ulonglong2 wR = *reinterpret_cast<const ulonglong2*>(wp + 16 + 2 * cp2);
                    conv_out(&acc0[cp2 * 4], caA, saA, r1A, wL, wC, wR);
                    conv_out(&acc1[cp2 * 4], caB, saB, r1B, wL, wC, wR);
                }
                if (kh < 2) {
                    caA = caB; saA = saB; r1A = r1B;    // renamed away by unroll
                    int off = (hr0 + kh + 2) * ROWP + w0;
                    caB = *reinterpret_cast<const ulonglong2*>(&scb[off]);
                    saB = *reinterpret_cast<const ulonglong2*>(&ssb[off]);
                    r1B = *reinterpret_cast<const u64*>(&ssb[off + 4]);
                }
            }
        }
    }

    // --- epilogue: activation chain + bias, vectorized coalesced stores ---
    #pragma unroll
    for (int co = 0; co < 8; ++co) {
        float bb = bias[co];
        const int cp2 = co >> 1, sub = (co & 1) * 2;
        const size_t cbase = ((size_t)((b * 8 + co) * 32 + dpos) << 14) + w0;
        #pragma unroll
        for (int o = 0; o < 2; ++o) {
            const u64* A = (o == 0) ? acc0 : acc1;
            float2 p0 = up2(A[cp2 * 4 + sub]);
            float2 p1 = up2(A[cp2 * 4 + sub + 1]);
            float4 r;
            r.x = act_chain(p0.x) + bb;
            r.y = act_chain(p0.y) + bb;
            r.z = act_chain(p1.x) + bb;
            r.w = act_chain(p1.y) + bb;
            *reinterpret_cast<float4*>(out + cbase + ((h0 + hr0 + o) << 7)) = r;
        }
    }
}

extern "C" void kernel_launch(void* const* d_in, const int* in_sizes, int n_in,
                              void* d_out, int out_size)
{
    const float* x    = (const float*)d_in[0];   // (8,8,32,128,128)
    const float* wgt  = (const float*)d_in[1];   // (8,8,3,3,3)
    const float* bias = (const float*)d_in[2];   // (8,1,1,1)
    float* out = (float*)d_out;                  // (8,8,32,128,128)

    weight_splat_kernel<<<1, 256>>>(wgt);
    void* gw_ptr = nullptr;
    cudaGetSymbolAddress(&gw_ptr, gW_buf);
    cudaMemcpyToSymbolAsync(cW, gw_ptr, 1728 * sizeof(u64), 0,
                            cudaMemcpyDeviceToDevice, 0);
    // grid = 4096 blocks of 128 threads; bx = b*512 + ht*32 + dpos
    conv3d_fused_kernel<<<4096, 128>>>(x, bias, out);
}